// round 8
// baseline (speedup 1.0000x reference)
#include <cuda_runtime.h>

// ---------------------------------------------------------------------------
// Problem constants
// ---------------------------------------------------------------------------
#define E_DIM 512      // embedding / hidden dim of rnn_first and rnn_second
#define T_LEN 256      // sentence length
#define G3    1536     // 3 * hidden (gate rows)
#define POOL_OUT 128

// Scan-kernel geometry: 32 CTAs per sentence group, 192 threads each.
// Each CTA owns 16 hidden units => 48 rows of Whh, weights register-resident.
#define NCTA 32
#define SCAN_THREADS 192
#define CNT_PER_GROUP 518   // 256 + 256 + 2 + 2 + 2 step counters per sentence

// ---------------------------------------------------------------------------
// Scratch buffers (static __device__ globals; no allocation anywhere)
// ---------------------------------------------------------------------------
__device__ float d_x  [2 * T_LEN * E_DIM];   // embedded input
__device__ float d_gi [2 * T_LEN * G3];      // precomputed input gates (big)
__device__ float d_yl0[2 * T_LEN * E_DIM];   // epoch0 layer0 outputs
__device__ float d_yl1[2 * T_LEN * E_DIM];   // epoch0 layer1 outputs
__device__ float d_gis[2 * 2 * G3];          // small gi (epoch1 layers / rnn2)
__device__ float d_ys0[2 * 2 * E_DIM];       // epoch1 layer0 outputs
__device__ float d_ys1[2 * 2 * E_DIM];       // epoch1 layer1 outputs
__device__ float d_ys2[2 * 2 * E_DIM];       // rnn2 outputs
__device__ int   d_cnt[2 * CNT_PER_GROUP];   // cross-CTA step counters

__device__ __forceinline__ float sigmoidf_(float x) { return 1.0f / (1.0f + expf(-x)); }

// ---------------------------------------------------------------------------
// Counter reset (must run at the head of every launch -> graph-replay safe)
// ---------------------------------------------------------------------------
__global__ void zero_cnt_kernel() {
    int i = blockIdx.x * 256 + threadIdx.x;
    if (i < 2 * CNT_PER_GROUP) d_cnt[i] = 0;
}

// ---------------------------------------------------------------------------
// Embedding gather: d_x[s][t][:] = emb[sent[t]]
// ---------------------------------------------------------------------------
__global__ void embed_kernel(const int* __restrict__ sA, const int* __restrict__ sB,
                             const float* __restrict__ emb) {
    int row = blockIdx.x;                 // 0..511  (s*256 + t)
    int s = row >> 8, t = row & 255;
    int tok = (s ? sB : sA)[t];
    const float4* src = (const float4*)(emb + (size_t)tok * E_DIM);
    float4* dst = (float4*)(d_x + (size_t)row * E_DIM);
    for (int i = threadIdx.x; i < E_DIM / 4; i += blockDim.x) dst[i] = src[i];
}

// ---------------------------------------------------------------------------
// Tiled fp32 NT-GEMM:  C[m][n] = sum_k A[m][k] * B[n][k] + bias[n]
// A: [M][K] row-major, B: [N][K] row-major.  M,N,K multiples of 64/64/16.
// 64x64 tile, BK=16, 256 threads, 4x4 register tile per thread.
// ---------------------------------------------------------------------------
__global__ __launch_bounds__(256)
void gemm_nt_kernel(const float* __restrict__ A, const float* __restrict__ B,
                    const float* __restrict__ bias, float* __restrict__ C,
                    int M, int N, int K) {
    __shared__ float As[16][64];
    __shared__ float Bs[16][64];
    int bm = blockIdx.y * 64;
    int bn = blockIdx.x * 64;
    int tid = threadIdx.x;
    int ty = tid / 16, tx = tid % 16;
    int lr = tid / 4;            // 0..63 tile row for loads
    int lc = (tid % 4) * 4;      // 0,4,8,12 k offset for loads

    float acc[4][4];
#pragma unroll
    for (int i = 0; i < 4; i++)
#pragma unroll
        for (int j = 0; j < 4; j++) acc[i][j] = 0.0f;

    for (int k0 = 0; k0 < K; k0 += 16) {
        float4 av = *(const float4*)(A + (size_t)(bm + lr) * K + k0 + lc);
        float4 bv = *(const float4*)(B + (size_t)(bn + lr) * K + k0 + lc);
        As[lc + 0][lr] = av.x; As[lc + 1][lr] = av.y;
        As[lc + 2][lr] = av.z; As[lc + 3][lr] = av.w;
        Bs[lc + 0][lr] = bv.x; Bs[lc + 1][lr] = bv.y;
        Bs[lc + 2][lr] = bv.z; Bs[lc + 3][lr] = bv.w;
        __syncthreads();
#pragma unroll
        for (int kk = 0; kk < 16; kk++) {
            float4 a = *(const float4*)(&As[kk][ty * 4]);
            float4 b = *(const float4*)(&Bs[kk][tx * 4]);
            acc[0][0] += a.x * b.x; acc[0][1] += a.x * b.y; acc[0][2] += a.x * b.z; acc[0][3] += a.x * b.w;
            acc[1][0] += a.y * b.x; acc[1][1] += a.y * b.y; acc[1][2] += a.y * b.z; acc[1][3] += a.y * b.w;
            acc[2][0] += a.z * b.x; acc[2][1] += a.z * b.y; acc[2][2] += a.z * b.z; acc[2][3] += a.z * b.w;
            acc[3][0] += a.w * b.x; acc[3][1] += a.w * b.y; acc[3][2] += a.w * b.z; acc[3][3] += a.w * b.w;
        }
        __syncthreads();
    }
#pragma unroll
    for (int i = 0; i < 4; i++) {
        int row = bm + ty * 4 + i;
#pragma unroll
        for (int j = 0; j < 4; j++) {
            int col = bn + tx * 4 + j;
            C[(size_t)row * N + col] = acc[i][j] + bias[col];
        }
    }
}

// ---------------------------------------------------------------------------
// Small gi GEMM for the tiny (seq-len 2) scans:
//   out[s][t][n] = dot(x(s,t), W[n]) + b[n],  K = 512
//   x(s,t) = (t ? p1 : p0) + s*strideS
// grid (12, 2, 2) x 128 threads
// ---------------------------------------------------------------------------
__global__ void small_gemm_kernel(const float* __restrict__ p0, const float* __restrict__ p1,
                                  long strideS, const float* __restrict__ W,
                                  const float* __restrict__ b, float* __restrict__ out) {
    int n = blockIdx.x * 128 + threadIdx.x;
    int t = blockIdx.y, s = blockIdx.z;
    const float* x = (t ? p1 : p0) + (size_t)s * strideS;
    const float4* xv = (const float4*)x;
    const float4* wv = (const float4*)(W + (size_t)n * 512);
    float a0 = 0.f, a1 = 0.f, a2 = 0.f, a3 = 0.f;
#pragma unroll 8
    for (int i = 0; i < 128; i += 4) {
        float4 xa = xv[i + 0], wa = wv[i + 0];
        a0 += xa.x * wa.x + xa.y * wa.y + xa.z * wa.z + xa.w * wa.w;
        float4 xb = xv[i + 1], wb = wv[i + 1];
        a1 += xb.x * wb.x + xb.y * wb.y + xb.z * wb.z + xb.w * wb.w;
        float4 xc = xv[i + 2], wc = wv[i + 2];
        a2 += xc.x * wc.x + xc.y * wc.y + xc.z * wc.z + xc.w * wc.w;
        float4 xd = xv[i + 3], wd = wv[i + 3];
        a3 += xd.x * wd.x + xd.y * wd.y + xd.z * wd.z + xd.w * wd.w;
    }
    out[(size_t)(s * 2 + t) * G3 + n] = a0 + a1 + a2 + a3 + b[n];
}

// ---------------------------------------------------------------------------
// Multi-CTA cooperative GRU scan.
//   grid (NCTA, 2): blockIdx.y = sentence, blockIdx.x = CTA within group.
//   Each CTA owns 16 hidden units => rows {u, 512+u, 1024+u : u in [u0,u0+16)}.
//   Weights for those 48 rows live in registers (128 floats / thread).
//   y[t] (the output sequence) doubles as the hidden-state exchange buffer;
//   a per-step global counter gates reads of y[t-1].
// ---------------------------------------------------------------------------
__global__ __launch_bounds__(SCAN_THREADS, 1)
void gru_scan_kernel(const float* __restrict__ gi, const float* __restrict__ Whh,
                     const float* __restrict__ bhh, float* __restrict__ y,
                     int T, int cntBase) {
    const int C = NCTA;
    int s   = blockIdx.y;
    int cta = blockIdx.x;
    int tid = threadIdx.x;
    int r    = tid % 48;         // row-local within the CTA's 48 rows
    int q    = tid / 48;         // k-quarter (0..3), 128 elements each
    int gate = r / 16;
    int ul   = r % 16;
    int u0   = cta * 16;
    int row  = gate * 512 + u0 + ul;
    int k0   = q * 128;

    // Register-resident weight slice: Whh[row][k0 .. k0+128)
    float4 w[32];
    const float4* wp = (const float4*)(Whh + (size_t)row * 512 + k0);
#pragma unroll
    for (int i = 0; i < 32; i++) w[i] = wp[i];
    float bh = (tid < 48) ? bhh[row] : 0.0f;

    __shared__ float h_sh[512];
    __shared__ float part[SCAN_THREADS];
    __shared__ float gh_sh[48];

    const float* gi_s = gi + (size_t)s * T * G3;
    float* y_s = y + (size_t)s * T * 512;
    int* cnt_g = d_cnt + s * CNT_PER_GROUP + cntBase;

    for (int t = 0; t < T; ++t) {
        if (t == 0) {
            for (int i = tid; i < 512; i += SCAN_THREADS) h_sh[i] = 0.0f;
        } else {
            if (tid == 0) {
                volatile int* p = (volatile int*)(cnt_g + (t - 1));
                while (*p < C) { }
            }
            __syncthreads();
            __threadfence();   // acquire side
            const float4* hp = (const float4*)(y_s + (size_t)(t - 1) * 512);
            for (int i = tid; i < 128; i += SCAN_THREADS)
                ((float4*)h_sh)[i] = __ldcg(hp + i);
        }
        // prefetch input gates for this CTA's units (independent of h)
        float gir = 0.f, giz = 0.f, gin_ = 0.f;
        if (tid < 16) {
            const float* g = gi_s + (size_t)t * G3;
            gir  = __ldg(g + u0 + tid);
            giz  = __ldg(g + 512 + u0 + tid);
            gin_ = __ldg(g + 1024 + u0 + tid);
        }
        __syncthreads();
        float hprev = (tid < 16) ? h_sh[u0 + tid] : 0.0f;

        // partial dot: rows in registers, h broadcast from smem
        float a0 = 0.f, a1 = 0.f, a2 = 0.f, a3 = 0.f;
        const float4* hh = (const float4*)(h_sh + k0);
#pragma unroll
        for (int i = 0; i < 32; i += 4) {
            float4 h0 = hh[i + 0], h1 = hh[i + 1], h2 = hh[i + 2], h3 = hh[i + 3];
            a0 += w[i + 0].x * h0.x + w[i + 0].y * h0.y + w[i + 0].z * h0.z + w[i + 0].w * h0.w;
            a1 += w[i + 1].x * h1.x + w[i + 1].y * h1.y + w[i + 1].z * h1.z + w[i + 1].w * h1.w;
            a2 += w[i + 2].x * h2.x + w[i + 2].y * h2.y + w[i + 2].z * h2.z + w[i + 2].w * h2.w;
            a3 += w[i + 3].x * h3.x + w[i + 3].y * h3.y + w[i + 3].z * h3.z + w[i + 3].w * h3.w;
        }
        part[tid] = a0 + a1 + a2 + a3;
        __syncthreads();
        if (tid < 48)
            gh_sh[tid] = part[tid] + part[48 + tid] + part[96 + tid] + part[144 + tid] + bh;
        __syncthreads();
        if (tid < 16) {
            float rg = sigmoidf_(gir + gh_sh[tid]);
            float zg = sigmoidf_(giz + gh_sh[16 + tid]);
            float ng = tanhf(gin_ + rg * gh_sh[32 + tid]);
            float hn = (1.0f - zg) * ng + zg * hprev;
            __stcg(y_s + (size_t)t * 512 + u0 + tid, hn);
        }
        __syncthreads();
        __threadfence();   // make y[t] writes visible before the counter bump
        if (tid == 0) atomicAdd(cnt_g + t, 1);
    }
}

// ---------------------------------------------------------------------------
// conv1d (2ch, k=512, stride 2, pad 255) + maxpool1d (k=512, stride 2, pad 255)
// + gi2 = pooled @ Wih2.T + bih2.   One CTA per sentence.
// ---------------------------------------------------------------------------
__global__ void conv_pool_gi2_kernel(const float* __restrict__ ys0, const float* __restrict__ ys1,
                                     const float* __restrict__ conv_w, const float* __restrict__ conv_b,
                                     const float* __restrict__ Wih2, const float* __restrict__ bih2,
                                     float* __restrict__ gi2) {
    int s = blockIdx.x;
    int tid = threadIdx.x;   // 256
    __shared__ float x_sh[2][512];
    __shared__ float y_sh[2][256];
    __shared__ float pooled[2][POOL_OUT];
    const float* c0 = ys0 + (size_t)(s * 2 + 1) * 512;   // epoch1 layer0 final
    const float* c1 = ys1 + (size_t)(s * 2 + 1) * 512;   // epoch1 layer1 final
    for (int i = tid; i < 512; i += 256) { x_sh[0][i] = c0[i]; x_sh[1][i] = c1[i]; }
    __syncthreads();

    // conv: out[o][j], j = tid
    for (int o = 0; o < 2; o++) {
        int j = tid;
        float acc = conv_b[o];
        int base = 2 * j - 255;
        for (int ic = 0; ic < 2; ic++) {
            const float* wr = conv_w + ((size_t)o * 2 + ic) * 512;
            int klo = base < 0 ? -base : 0;
            int khi = 512 - base; if (khi > 512) khi = 512;
            for (int k = klo; k < khi; k++) acc += x_sh[ic][base + k] * __ldg(wr + k);
        }
        y_sh[o][j] = acc;
    }
    __syncthreads();

    // maxpool (literal window; for these sizes it covers the full row)
    for (int i = tid; i < 2 * POOL_OUT; i += 256) {
        int o = i >> 7, p = i & 127;
        int lo = 2 * p - 255; if (lo < 0) lo = 0;
        int hi = 2 * p + 256; if (hi > 255) hi = 255;
        float m = -3.402823e38f;
        for (int qq = lo; qq <= hi; qq++) m = fmaxf(m, y_sh[o][qq]);
        pooled[o][p] = m;
    }
    __syncthreads();

    // gi2[s][t][n] = dot(pooled[t], Wih2[n]) + bih2[n]
    for (int i = tid; i < 2 * G3; i += 256) {
        int t = i / G3, n = i % G3;
        const float* wr = Wih2 + (size_t)n * POOL_OUT;
        float acc = bih2[n];
        for (int p = 0; p < POOL_OUT; p++) acc += pooled[t][p] * __ldg(wr + p);
        gi2[(size_t)(s * 2 + t) * G3 + n] = acc;
    }
}

// ---------------------------------------------------------------------------
// Final head: hx = hA*hB, hv = |hA-hB|, hs = hx@WA + hv@WB + b, tanh,
//             out = sigmoid(ht @ W_lin.T + b_lin)
// ---------------------------------------------------------------------------
__global__ void final_kernel(const float* __restrict__ ys2,
                             const float* __restrict__ WA, const float* __restrict__ WB,
                             const float* __restrict__ b_bi, const float* __restrict__ W_lin,
                             const float* __restrict__ b_lin, float* __restrict__ out) {
    __shared__ float hx[512], hv[512];
    __shared__ float red[256];
    const float* hA = ys2 + 1 * 512;   // ys2[0][1]
    const float* hB = ys2 + 3 * 512;   // ys2[1][1]
    int tid = threadIdx.x;             // 256
    for (int i = tid; i < 512; i += 256) {
        float a = hA[i], b = hB[i];
        hx[i] = a * b;
        hv[i] = fabsf(a - b);
    }
    __syncthreads();
    float acc = b_bi[tid];
    for (int h = 0; h < 512; h++)
        acc += hx[h] * __ldg(WA + (size_t)h * 256 + tid) + hv[h] * __ldg(WB + (size_t)h * 256 + tid);
    float ht = tanhf(acc);
    red[tid] = ht * __ldg(W_lin + tid);
    __syncthreads();
    for (int off = 128; off > 0; off >>= 1) {
        if (tid < off) red[tid] += red[tid + off];
        __syncthreads();
    }
    if (tid == 0) out[0] = 1.0f / (1.0f + expf(-(red[0] + b_lin[0])));
}

// ---------------------------------------------------------------------------
// Host launcher
// ---------------------------------------------------------------------------
static void* sym_addr(const void* sym) {
    void* p = nullptr;
    cudaGetSymbolAddress(&p, sym);
    return p;
}

extern "C" void kernel_launch(void* const* d_in, const int* in_sizes, int n_in,
                              void* d_out, int out_size) {
    const int*   sentA  = (const int*)  d_in[0];
    const int*   sentB  = (const int*)  d_in[1];
    const float* emb    = (const float*)d_in[2];
    const float* Wih1   = (const float*)d_in[3];   // [2][1536][512]
    const float* Whh1   = (const float*)d_in[4];   // [2][1536][512]
    const float* bih1   = (const float*)d_in[5];   // [2][1536]
    const float* bhh1   = (const float*)d_in[6];   // [2][1536]
    const float* conv_w = (const float*)d_in[7];   // [2][2][512]
    const float* conv_b = (const float*)d_in[8];   // [2]
    const float* Wih2   = (const float*)d_in[9];   // [1536][128]
    const float* Whh2   = (const float*)d_in[10];  // [1536][512]
    const float* bih2   = (const float*)d_in[11];  // [1536]
    const float* bhh2   = (const float*)d_in[12];  // [1536]
    const float* WA     = (const float*)d_in[13];  // [512][256]
    const float* WB     = (const float*)d_in[14];  // [512][256]
    const float* b_bi   = (const float*)d_in[15];  // [256]
    const float* W_lin  = (const float*)d_in[16];  // [1][256]
    const float* b_lin  = (const float*)d_in[17];  // [1]
    (void)in_sizes; (void)n_in; (void)out_size;

    float* px   = (float*)sym_addr(d_x);
    float* pgi  = (float*)sym_addr(d_gi);
    float* pyl0 = (float*)sym_addr(d_yl0);
    float* pyl1 = (float*)sym_addr(d_yl1);
    float* pgis = (float*)sym_addr(d_gis);
    float* pys0 = (float*)sym_addr(d_ys0);
    float* pys1 = (float*)sym_addr(d_ys1);
    float* pys2 = (float*)sym_addr(d_ys2);

    const float* Wih1_l1 = Wih1 + (size_t)G3 * 512;
    const float* Whh1_l1 = Whh1 + (size_t)G3 * 512;
    const float* bih1_l1 = bih1 + G3;
    const float* bhh1_l1 = bhh1 + G3;

    dim3 gemm_grid(G3 / 64, 512 / 64);      // N tiles x M tiles
    dim3 scan_grid(NCTA, 2);
    dim3 small_grid(G3 / 128, 2, 2);

    // 0. reset step counters (graph-replay safe)
    zero_cnt_kernel<<<5, 256>>>();

    // 1. embedding gather
    embed_kernel<<<512, 128>>>(sentA, sentB, emb);

    // ---- epoch 0 ----
    // layer 0
    gemm_nt_kernel<<<gemm_grid, 256>>>(px, Wih1, bih1, pgi, 512, G3, 512);
    gru_scan_kernel<<<scan_grid, SCAN_THREADS>>>(pgi, Whh1, bhh1, pyl0, T_LEN, 0);
    // layer 1
    gemm_nt_kernel<<<gemm_grid, 256>>>(pyl0, Wih1_l1, bih1_l1, pgi, 512, G3, 512);
    gru_scan_kernel<<<scan_grid, SCAN_THREADS>>>(pgi, Whh1_l1, bhh1_l1, pyl1, T_LEN, 256);

    // ---- epoch 1 (sequence = stacked finals of epoch 0, length 2) ----
    small_gemm_kernel<<<small_grid, 128>>>(pyl0 + 255 * 512, pyl1 + 255 * 512,
                                           (long)(T_LEN * 512), Wih1, bih1, pgis);
    gru_scan_kernel<<<scan_grid, SCAN_THREADS>>>(pgis, Whh1, bhh1, pys0, 2, 512);
    small_gemm_kernel<<<small_grid, 128>>>(pys0, pys0 + 512, (long)(2 * 512),
                                           Wih1_l1, bih1_l1, pgis);
    gru_scan_kernel<<<scan_grid, SCAN_THREADS>>>(pgis, Whh1_l1, bhh1_l1, pys1, 2, 514);

    // ---- conv + pool + gi2 ----
    conv_pool_gi2_kernel<<<2, 256>>>(pys0, pys1, conv_w, conv_b, Wih2, bih2, pgis);

    // ---- rnn_second (length 2) ----
    gru_scan_kernel<<<scan_grid, SCAN_THREADS>>>(pgis, Whh2, bhh2, pys2, 2, 516);

    // ---- head ----
    final_kernel<<<1, 256>>>(pys2, WA, WB, b_bi, W_lin, b_lin, (float*)d_out);
}

// round 9
// speedup vs baseline: 1.1427x; 1.1427x over previous
#include <cuda_runtime.h>

// ---------------------------------------------------------------------------
// Problem constants
// ---------------------------------------------------------------------------
#define E_DIM 512      // embedding / hidden dim of rnn_first and rnn_second
#define T_LEN 256      // sentence length
#define G3    1536     // 3 * hidden (gate rows)
#define POOL_OUT 128

#define NCTA 32               // CTAs per (sentence, layer) group
#define FUSED_THREADS 384
#define SCAN_THREADS 192
#define CNT_PER_GROUP 518

// ---------------------------------------------------------------------------
// Scratch buffers (static __device__ globals; no allocation anywhere)
// ---------------------------------------------------------------------------
__device__ float d_x  [2 * T_LEN * E_DIM];   // embedded input
__device__ float d_yl0[2 * T_LEN * E_DIM];   // epoch0 layer0 outputs
__device__ float d_yl1[2 * T_LEN * E_DIM];   // epoch0 layer1 outputs
__device__ float d_gis[2 * 2 * G3];          // small gi (epoch1 layers / rnn2)
__device__ float d_ys0[2 * 2 * E_DIM];       // epoch1 layer0 outputs
__device__ float d_ys1[2 * 2 * E_DIM];       // epoch1 layer1 outputs
__device__ float d_ys2[2 * 2 * E_DIM];       // rnn2 outputs
__device__ int   d_cnt[2 * CNT_PER_GROUP];   // step counters (small scans)
__device__ int   d_flag[2][2][NCTA];         // per-CTA step flags (fused scan)

__device__ __forceinline__ float sigmoidf_(float x) { return 1.0f / (1.0f + expf(-x)); }

// packed fp32x2 FMA: d = a*b + d (pairwise) — only reachable via PTX
__device__ __forceinline__ void ffma2(unsigned long long& d,
                                      unsigned long long a, unsigned long long b) {
    asm("fma.rn.f32x2 %0, %1, %2, %0;" : "+l"(d) : "l"(a), "l"(b));
}
__device__ __forceinline__ float pairsum(unsigned long long v) {
    float lo = __uint_as_float((unsigned)(v & 0xffffffffull));
    float hi = __uint_as_float((unsigned)(v >> 32));
    return lo + hi;
}

// ---------------------------------------------------------------------------
// Counter/flag reset (head of every launch -> graph-replay safe)
// ---------------------------------------------------------------------------
__global__ void zero_cnt_kernel() {
    int i = blockIdx.x * 256 + threadIdx.x;
    if (i < 2 * CNT_PER_GROUP) d_cnt[i] = 0;
    int j = i - 2 * CNT_PER_GROUP;
    if (j >= 0 && j < 2 * 2 * NCTA) ((int*)d_flag)[j] = 0;
}

// ---------------------------------------------------------------------------
// Embedding gather: d_x[s][t][:] = emb[sent[t]]
// ---------------------------------------------------------------------------
__global__ void embed_kernel(const int* __restrict__ sA, const int* __restrict__ sB,
                             const float* __restrict__ emb) {
    int row = blockIdx.x;                 // 0..511  (s*256 + t)
    int s = row >> 8, t = row & 255;
    int tok = (s ? sB : sA)[t];
    const float4* src = (const float4*)(emb + (size_t)tok * E_DIM);
    float4* dst = (float4*)(d_x + (size_t)row * E_DIM);
    for (int i = threadIdx.x; i < E_DIM / 4; i += blockDim.x) dst[i] = src[i];
}

// ---------------------------------------------------------------------------
// Fused epoch-0 scan: both GRU layers, both sentences, gi computed on the fly.
//   grid (NCTA, 2 layers, 2 sentences) x 384 threads. All 128 CTAs resident.
//   Each CTA owns 16 hidden units => 48 Wih rows + 48 Whh rows, all weights
//   register-resident as packed f32x2 (128 floats = 64 b64 regs per thread).
//   Thread split: m = tid/192 selects gi (Wih·x) vs gh (Whh·h);
//                 within m: r = idx%48 row, q = idx/48 k-quarter of 128.
//   Sync: per-CTA monotonic flag (distinct addresses, no atomic contention).
//   Layer 1 consumes y0[t] produced by layer 0 in the same launch (1-step lag).
// ---------------------------------------------------------------------------
__global__ __launch_bounds__(FUSED_THREADS, 1)
void fused_scan_kernel(const float* __restrict__ Wih, const float* __restrict__ Whh,
                       const float* __restrict__ bih, const float* __restrict__ bhh) {
    int cta   = blockIdx.x;   // 0..31
    int layer = blockIdx.y;   // 0..1
    int s     = blockIdx.z;   // 0..1
    int tid   = threadIdx.x;  // 0..383
    int m   = tid / 192;      // 0: gi (Wih, input x), 1: gh (Whh, hidden h)
    int idx = tid % 192;
    int r   = idx % 48;
    int q   = idx / 48;       // k-quarter
    int gate = r / 16, ul = r % 16;
    int u0  = cta * 16;
    int row = gate * 512 + u0 + ul;
    int k0  = q * 128;

    // register-resident weight slice (128 floats as 64 b64 regs)
    const float* Wsel = (m == 0 ? Wih : Whh) + (size_t)layer * G3 * 512;
    ulonglong2 w2[32];
    const ulonglong2* wp = (const ulonglong2*)(Wsel + (size_t)row * 512 + k0);
#pragma unroll
    for (int i = 0; i < 32; i++) w2[i] = wp[i];

    // bias for the combiner threads (tid<96): m2 = tid/48, r2 = tid%48
    float bias = 0.0f;
    if (tid < 96) {
        int m2 = tid / 48, r2 = tid % 48;
        int rrow = (r2 / 16) * 512 + u0 + (r2 % 16);
        bias = ((m2 == 0) ? bih : bhh)[(size_t)layer * G3 + rrow];
    }

    __shared__ __align__(16) float x_sh[512];
    __shared__ __align__(16) float h_sh[512];
    __shared__ float part[FUSED_THREADS];
    __shared__ float g_sh[2][48];

    const float* xsrc_base = (layer == 0)
        ? (d_x   + (size_t)s * T_LEN * 512)
        : (d_yl0 + (size_t)s * T_LEN * 512);
    float* ybase = ((layer == 0) ? d_yl0 : d_yl1) + (size_t)s * T_LEN * 512;
    volatile int* fown = (volatile int*)&d_flag[s][layer][0];
    volatile int* fprv = (volatile int*)&d_flag[s][0][0];

    for (int t = 0; t < T_LEN; ++t) {
        // ---- wait for dependencies (warp 0, one flag per lane) ----
        if (tid < 32) {
            if (layer == 1) {
                while (fprv[tid] < t + 1) { }   // y0[t] ready
            }
            if (t > 0) {
                while (fown[tid] < t) { }       // own-layer h[t-1] ready
            }
        }
        __syncthreads();   // also protects x_sh/h_sh reuse from previous step

        // ---- load x[t] and h[t-1] into smem ----
        if (tid < 128) {
            const float4* xs = (const float4*)(xsrc_base + (size_t)t * 512);
            ((float4*)x_sh)[tid] = (layer == 0) ? __ldg(xs + tid) : __ldcg(xs + tid);
        } else if (tid < 256) {
            int i = tid - 128;
            if (t == 0) ((float4*)h_sh)[i] = make_float4(0.f, 0.f, 0.f, 0.f);
            else ((float4*)h_sh)[i] =
                __ldcg((const float4*)(ybase + (size_t)(t - 1) * 512) + i);
        }
        __syncthreads();

        // ---- matvec: weights in regs, vector broadcast from smem ----
        const ulonglong2* vin = (const ulonglong2*)((m == 0 ? x_sh : h_sh) + k0);
        unsigned long long accA = 0ull, accB = 0ull;
#pragma unroll 8
        for (int i = 0; i < 32; i++) {
            ulonglong2 hv = vin[i];
            ffma2(accA, w2[i].x, hv.x);
            ffma2(accB, w2[i].y, hv.y);
        }
        part[tid] = pairsum(accA) + pairsum(accB);
        __syncthreads();

        if (tid < 96) {
            int m2 = tid / 48, r2 = tid % 48, b = m2 * 192 + r2;
            g_sh[m2][r2] = part[b] + part[b + 48] + part[b + 96] + part[b + 144] + bias;
        }
        __syncthreads();

        // ---- gates + state update + publish ----
        if (tid < 16) {
            float rg = sigmoidf_(g_sh[0][tid]      + g_sh[1][tid]);
            float zg = sigmoidf_(g_sh[0][16 + tid] + g_sh[1][16 + tid]);
            float ng = tanhf   (g_sh[0][32 + tid] + rg * g_sh[1][32 + tid]);
            float hprev = h_sh[u0 + tid];
            float hn = (1.0f - zg) * ng + zg * hprev;
            __stcg(ybase + (size_t)t * 512 + u0 + tid, hn);
        }
        if (tid < 32) {
            __threadfence();              // order the 16 h-stores before the flag
            __syncwarp();
            if (tid == 0) __stcg((int*)(fown + cta), t + 1);
        }
    }
}

// ---------------------------------------------------------------------------
// Small gi GEMM for the tiny (seq-len 2) scans:
//   out[s][t][n] = dot(x(s,t), W[n]) + b[n],  K = 512
// ---------------------------------------------------------------------------
__global__ void small_gemm_kernel(const float* __restrict__ p0, const float* __restrict__ p1,
                                  long strideS, const float* __restrict__ W,
                                  const float* __restrict__ b, float* __restrict__ out) {
    int n = blockIdx.x * 128 + threadIdx.x;
    int t = blockIdx.y, s = blockIdx.z;
    const float* x = (t ? p1 : p0) + (size_t)s * strideS;
    const float4* xv = (const float4*)x;
    const float4* wv = (const float4*)(W + (size_t)n * 512);
    float a0 = 0.f, a1 = 0.f, a2 = 0.f, a3 = 0.f;
#pragma unroll 8
    for (int i = 0; i < 128; i += 4) {
        float4 xa = xv[i + 0], wa = wv[i + 0];
        a0 += xa.x * wa.x + xa.y * wa.y + xa.z * wa.z + xa.w * wa.w;
        float4 xb = xv[i + 1], wb = wv[i + 1];
        a1 += xb.x * wb.x + xb.y * wb.y + xb.z * wb.z + xb.w * wb.w;
        float4 xc = xv[i + 2], wc = wv[i + 2];
        a2 += xc.x * wc.x + xc.y * wc.y + xc.z * wc.z + xc.w * wc.w;
        float4 xd = xv[i + 3], wd = wv[i + 3];
        a3 += xd.x * wd.x + xd.y * wd.y + xd.z * wd.z + xd.w * wd.w;
    }
    out[(size_t)(s * 2 + t) * G3 + n] = a0 + a1 + a2 + a3 + b[n];
}

// ---------------------------------------------------------------------------
// Multi-CTA cooperative GRU scan (seq-len 2 uses only; unchanged from R7).
// ---------------------------------------------------------------------------
__global__ __launch_bounds__(SCAN_THREADS, 1)
void gru_scan_kernel(const float* __restrict__ gi, const float* __restrict__ Whh,
                     const float* __restrict__ bhh, float* __restrict__ y,
                     int T, int cntBase) {
    const int C = NCTA;
    int s   = blockIdx.y;
    int cta = blockIdx.x;
    int tid = threadIdx.x;
    int r    = tid % 48;
    int q    = tid / 48;
    int gate = r / 16;
    int ul   = r % 16;
    int u0   = cta * 16;
    int row  = gate * 512 + u0 + ul;
    int k0   = q * 128;

    float4 w[32];
    const float4* wp = (const float4*)(Whh + (size_t)row * 512 + k0);
#pragma unroll
    for (int i = 0; i < 32; i++) w[i] = wp[i];
    float bh = (tid < 48) ? bhh[row] : 0.0f;

    __shared__ __align__(16) float h_sh[512];
    __shared__ float part[SCAN_THREADS];
    __shared__ float gh_sh[48];

    const float* gi_s = gi + (size_t)s * T * G3;
    float* y_s = y + (size_t)s * T * 512;
    int* cnt_g = d_cnt + s * CNT_PER_GROUP + cntBase;

    for (int t = 0; t < T; ++t) {
        if (t == 0) {
            for (int i = tid; i < 512; i += SCAN_THREADS) h_sh[i] = 0.0f;
        } else {
            if (tid == 0) {
                volatile int* p = (volatile int*)(cnt_g + (t - 1));
                while (*p < C) { }
            }
            __syncthreads();
            __threadfence();
            const float4* hp = (const float4*)(y_s + (size_t)(t - 1) * 512);
            for (int i = tid; i < 128; i += SCAN_THREADS)
                ((float4*)h_sh)[i] = __ldcg(hp + i);
        }
        float gir = 0.f, giz = 0.f, gin_ = 0.f;
        if (tid < 16) {
            const float* g = gi_s + (size_t)t * G3;
            gir  = __ldg(g + u0 + tid);
            giz  = __ldg(g + 512 + u0 + tid);
            gin_ = __ldg(g + 1024 + u0 + tid);
        }
        __syncthreads();
        float hprev = (tid < 16) ? h_sh[u0 + tid] : 0.0f;

        float a0 = 0.f, a1 = 0.f, a2 = 0.f, a3 = 0.f;
        const float4* hh = (const float4*)(h_sh + k0);
#pragma unroll
        for (int i = 0; i < 32; i += 4) {
            float4 h0 = hh[i + 0], h1 = hh[i + 1], h2 = hh[i + 2], h3 = hh[i + 3];
            a0 += w[i + 0].x * h0.x + w[i + 0].y * h0.y + w[i + 0].z * h0.z + w[i + 0].w * h0.w;
            a1 += w[i + 1].x * h1.x + w[i + 1].y * h1.y + w[i + 1].z * h1.z + w[i + 1].w * h1.w;
            a2 += w[i + 2].x * h2.x + w[i + 2].y * h2.y + w[i + 2].z * h2.z + w[i + 2].w * h2.w;
            a3 += w[i + 3].x * h3.x + w[i + 3].y * h3.y + w[i + 3].z * h3.z + w[i + 3].w * h3.w;
        }
        part[tid] = a0 + a1 + a2 + a3;
        __syncthreads();
        if (tid < 48)
            gh_sh[tid] = part[tid] + part[48 + tid] + part[96 + tid] + part[144 + tid] + bh;
        __syncthreads();
        if (tid < 16) {
            float rg = sigmoidf_(gir + gh_sh[tid]);
            float zg = sigmoidf_(giz + gh_sh[16 + tid]);
            float ng = tanhf(gin_ + rg * gh_sh[32 + tid]);
            float hn = (1.0f - zg) * ng + zg * hprev;
            __stcg(y_s + (size_t)t * 512 + u0 + tid, hn);
        }
        __syncthreads();
        __threadfence();
        if (tid == 0) atomicAdd(cnt_g + t, 1);
    }
}

// ---------------------------------------------------------------------------
// conv1d + maxpool1d + gi2 (one CTA per sentence) — unchanged.
// ---------------------------------------------------------------------------
__global__ void conv_pool_gi2_kernel(const float* __restrict__ ys0, const float* __restrict__ ys1,
                                     const float* __restrict__ conv_w, const float* __restrict__ conv_b,
                                     const float* __restrict__ Wih2, const float* __restrict__ bih2,
                                     float* __restrict__ gi2) {
    int s = blockIdx.x;
    int tid = threadIdx.x;   // 256
    __shared__ float x_sh[2][512];
    __shared__ float y_sh[2][256];
    __shared__ float pooled[2][POOL_OUT];
    const float* c0 = ys0 + (size_t)(s * 2 + 1) * 512;
    const float* c1 = ys1 + (size_t)(s * 2 + 1) * 512;
    for (int i = tid; i < 512; i += 256) { x_sh[0][i] = c0[i]; x_sh[1][i] = c1[i]; }
    __syncthreads();

    for (int o = 0; o < 2; o++) {
        int j = tid;
        float acc = conv_b[o];
        int base = 2 * j - 255;
        for (int ic = 0; ic < 2; ic++) {
            const float* wr = conv_w + ((size_t)o * 2 + ic) * 512;
            int klo = base < 0 ? -base : 0;
            int khi = 512 - base; if (khi > 512) khi = 512;
            for (int k = klo; k < khi; k++) acc += x_sh[ic][base + k] * __ldg(wr + k);
        }
        y_sh[o][j] = acc;
    }
    __syncthreads();

    for (int i = tid; i < 2 * POOL_OUT; i += 256) {
        int o = i >> 7, p = i & 127;
        int lo = 2 * p - 255; if (lo < 0) lo = 0;
        int hi = 2 * p + 256; if (hi > 255) hi = 255;
        float m = -3.402823e38f;
        for (int qq = lo; qq <= hi; qq++) m = fmaxf(m, y_sh[o][qq]);
        pooled[o][p] = m;
    }
    __syncthreads();

    for (int i = tid; i < 2 * G3; i += 256) {
        int t = i / G3, n = i % G3;
        const float* wr = Wih2 + (size_t)n * POOL_OUT;
        float acc = bih2[n];
        for (int p = 0; p < POOL_OUT; p++) acc += pooled[t][p] * __ldg(wr + p);
        gi2[(size_t)(s * 2 + t) * G3 + n] = acc;
    }
}

// ---------------------------------------------------------------------------
// Final head — unchanged.
// ---------------------------------------------------------------------------
__global__ void final_kernel(const float* __restrict__ ys2,
                             const float* __restrict__ WA, const float* __restrict__ WB,
                             const float* __restrict__ b_bi, const float* __restrict__ W_lin,
                             const float* __restrict__ b_lin, float* __restrict__ out) {
    __shared__ float hx[512], hv[512];
    __shared__ float red[256];
    const float* hA = ys2 + 1 * 512;
    const float* hB = ys2 + 3 * 512;
    int tid = threadIdx.x;             // 256
    for (int i = tid; i < 512; i += 256) {
        float a = hA[i], b = hB[i];
        hx[i] = a * b;
        hv[i] = fabsf(a - b);
    }
    __syncthreads();
    float acc = b_bi[tid];
    for (int h = 0; h < 512; h++)
        acc += hx[h] * __ldg(WA + (size_t)h * 256 + tid) + hv[h] * __ldg(WB + (size_t)h * 256 + tid);
    float ht = tanhf(acc);
    red[tid] = ht * __ldg(W_lin + tid);
    __syncthreads();
    for (int off = 128; off > 0; off >>= 1) {
        if (tid < off) red[tid] += red[tid + off];
        __syncthreads();
    }
    if (tid == 0) out[0] = 1.0f / (1.0f + expf(-(red[0] + b_lin[0])));
}

// ---------------------------------------------------------------------------
// Host launcher
// ---------------------------------------------------------------------------
static void* sym_addr(const void* sym) {
    void* p = nullptr;
    cudaGetSymbolAddress(&p, sym);
    return p;
}

extern "C" void kernel_launch(void* const* d_in, const int* in_sizes, int n_in,
                              void* d_out, int out_size) {
    const int*   sentA  = (const int*)  d_in[0];
    const int*   sentB  = (const int*)  d_in[1];
    const float* emb    = (const float*)d_in[2];
    const float* Wih1   = (const float*)d_in[3];   // [2][1536][512]
    const float* Whh1   = (const float*)d_in[4];   // [2][1536][512]
    const float* bih1   = (const float*)d_in[5];   // [2][1536]
    const float* bhh1   = (const float*)d_in[6];   // [2][1536]
    const float* conv_w = (const float*)d_in[7];   // [2][2][512]
    const float* conv_b = (const float*)d_in[8];   // [2]
    const float* Wih2   = (const float*)d_in[9];   // [1536][128]
    const float* Whh2   = (const float*)d_in[10];  // [1536][512]
    const float* bih2   = (const float*)d_in[11];  // [1536]
    const float* bhh2   = (const float*)d_in[12];  // [1536]
    const float* WA     = (const float*)d_in[13];  // [512][256]
    const float* WB     = (const float*)d_in[14];  // [512][256]
    const float* b_bi   = (const float*)d_in[15];  // [256]
    const float* W_lin  = (const float*)d_in[16];  // [1][256]
    const float* b_lin  = (const float*)d_in[17];  // [1]
    (void)in_sizes; (void)n_in; (void)out_size;

    float* pyl0 = (float*)sym_addr(d_yl0);
    float* pyl1 = (float*)sym_addr(d_yl1);
    float* pgis = (float*)sym_addr(d_gis);
    float* pys0 = (float*)sym_addr(d_ys0);
    float* pys1 = (float*)sym_addr(d_ys1);
    float* pys2 = (float*)sym_addr(d_ys2);

    const float* Wih1_l1 = Wih1 + (size_t)G3 * 512;
    const float* Whh1_l1 = Whh1 + (size_t)G3 * 512;
    const float* bih1_l1 = bih1 + G3;
    const float* bhh1_l1 = bhh1 + G3;

    dim3 fused_grid(NCTA, 2, 2);            // ctas x layers x sentences
    dim3 scan_grid(NCTA, 2);
    dim3 small_grid(G3 / 128, 2, 2);

    // 0. reset counters + flags (graph-replay safe)
    zero_cnt_kernel<<<6, 256>>>();

    // 1. embedding gather
    embed_kernel<<<512, 128>>>(sentA, sentB, emb);

    // ---- epoch 0: both layers fused, gi on the fly, layer-1 lags by 1 step ----
    fused_scan_kernel<<<fused_grid, FUSED_THREADS>>>(Wih1, Whh1, bih1, bhh1);

    // ---- epoch 1 (sequence = stacked finals of epoch 0, length 2) ----
    small_gemm_kernel<<<small_grid, 128>>>(pyl0 + 255 * 512, pyl1 + 255 * 512,
                                           (long)(T_LEN * 512), Wih1, bih1, pgis);
    gru_scan_kernel<<<scan_grid, SCAN_THREADS>>>(pgis, Whh1, bhh1, pys0, 2, 512);
    small_gemm_kernel<<<small_grid, 128>>>(pys0, pys0 + 512, (long)(2 * 512),
                                           Wih1_l1, bih1_l1, pgis);
    gru_scan_kernel<<<scan_grid, SCAN_THREADS>>>(pgis, Whh1_l1, bhh1_l1, pys1, 2, 514);

    // ---- conv + pool + gi2 ----
    conv_pool_gi2_kernel<<<2, 256>>>(pys0, pys1, conv_w, conv_b, Wih2, bih2, pgis);

    // ---- rnn_second (length 2) ----
    gru_scan_kernel<<<scan_grid, SCAN_THREADS>>>(pgis, Whh2, bhh2, pys2, 2, 516);

    // ---- head ----
    final_kernel<<<1, 256>>>(pys2, WA, WB, b_bi, W_lin, b_lin, (float*)d_out);
}

// round 11
// speedup vs baseline: 1.4397x; 1.2599x over previous
#include <cuda_runtime.h>

// ---------------------------------------------------------------------------
// Problem constants
// ---------------------------------------------------------------------------
#define E_DIM 512
#define T_LEN 256
#define G3    1536
#define POOL_OUT 128

#define NCTA 32              // CTAs per (sentence, role) group
#define STH  192             // scan/army threads per CTA
#define CNT_PER_GROUP 518

// ---------------------------------------------------------------------------
// Scratch (static __device__ globals; no allocation anywhere)
// ---------------------------------------------------------------------------
__device__ float d_gi [2 * T_LEN * G3];      // gi ring (reused per layer launch)
__device__ float d_yl0[2 * T_LEN * E_DIM];   // layer0 outputs
__device__ float d_yl1[2 * T_LEN * E_DIM];   // layer1 outputs
__device__ float d_gis[2 * 2 * G3];          // small gi (epoch1 / rnn2)
__device__ float d_ys0[2 * 2 * E_DIM];
__device__ float d_ys1[2 * 2 * E_DIM];
__device__ float d_ys2[2 * 2 * E_DIM];
__device__ int   d_cnt[2 * CNT_PER_GROUP];   // counters for tiny T=2 scans
__device__ int   d_flag[2][2][2][NCTA];      // [launch][sentence][role][cta]

__device__ __forceinline__ float sigmoidf_(float x) { return 1.0f / (1.0f + expf(-x)); }

// poll load: must not be hoisted; bypass L1
__device__ __forceinline__ int ldcg_poll(const int* p) {
    int v;
    asm volatile("ld.global.cg.s32 %0, [%1];" : "=r"(v) : "l"(p) : "memory");
    return v;
}

// ---------------------------------------------------------------------------
// Flag/counter reset (head of every launch -> graph-replay safe)
// ---------------------------------------------------------------------------
__global__ void zero_cnt_kernel() {
    int i = blockIdx.x * 256 + threadIdx.x;
    if (i < 2 * CNT_PER_GROUP) d_cnt[i] = 0;
    int j = i - 2 * CNT_PER_GROUP;
    if (j >= 0 && j < 2 * 2 * 2 * NCTA) ((int*)d_flag)[j] = 0;
}

// ---------------------------------------------------------------------------
// One GRU layer over T=256, both sentences, as army+scan CTA pairs.
//   grid (NCTA, 2 roles, 2 sentences) x 192 threads  => 128 resident CTAs.
//   role 0 (army): holds 48 rows of Wih in regs; free-runs gi[t] = Wih·x[t]+bih
//                  (x[t] = emb[sent[t]] for layer 0, y_prev[t] for layer 1),
//                  publishes flag[s][0][cta] = t+1.
//   role 1 (scan): holds 48 rows of Whh in regs; per step waits army flag
//                  (its own cta only) + all 32 scan flags for h[t-1], then
//                  gh = Whh·h + bhh, GRU gates, publishes h[t] + flag.
//   Release discipline (R8-proven): every storing lane executes __threadfence()
//   BEFORE the flag store; consumers fence after the flag wait.
// ---------------------------------------------------------------------------
__global__ __launch_bounds__(STH, 1)
void scan_layer_kernel(const float* __restrict__ Wih, const float* __restrict__ bih,
                       const float* __restrict__ Whh, const float* __restrict__ bhh,
                       const float* __restrict__ xbase,      // emb or y_prev
                       const int* __restrict__ idxA, const int* __restrict__ idxB,
                       float* __restrict__ gi_buf,           // [2][T][G3]
                       float* __restrict__ y,                // [2][T][512]
                       int bank) {
    int cta  = blockIdx.x;
    int role = blockIdx.y;    // 0 army, 1 scan
    int s    = blockIdx.z;
    int tid  = threadIdx.x;
    int r    = tid % 48;
    int q    = tid / 48;
    int gate = r / 16, ul = r % 16;
    int u0   = cta * 16;
    int row  = gate * 512 + u0 + ul;
    int k0   = q * 128;

    // register-resident weight slice (48 rows x 512, this thread: 128 floats)
    const float* W = (role == 0) ? Wih : Whh;
    float4 w[32];
    const float4* wp = (const float4*)(W + (size_t)row * 512 + k0);
#pragma unroll
    for (int i = 0; i < 32; i++) w[i] = wp[i];
    float bias = (tid < 48) ? ((role == 0) ? bih : bhh)[row] : 0.0f;

    __shared__ __align__(16) float v_sh[512];     // x[t] (army) or h[t-1] (scan)
    __shared__ float part[STH];
    __shared__ float g_sh[48];

    int* fArmy = &d_flag[bank][s][0][0];
    int* fScan = &d_flag[bank][s][1][0];
    float* y_s = y + (size_t)s * T_LEN * 512;
    float* gi_s = gi_buf + (size_t)s * T_LEN * G3;
    const int* idx = (s ? idxB : idxA);

    if (role == 0) {
        // ================= ARMY: gi producer (no waiting) =================
        for (int t = 0; t < T_LEN; ++t) {
            const float* xr = idxA
                ? (xbase + (size_t)idx[t] * 512)
                : (xbase + ((size_t)s * T_LEN + t) * 512);
            if (tid < 128) ((float4*)v_sh)[tid] = __ldg((const float4*)xr + tid);
            __syncthreads();

            float a0 = 0.f, a1 = 0.f, a2 = 0.f, a3 = 0.f;
            const float4* hh = (const float4*)(v_sh + k0);
#pragma unroll
            for (int i = 0; i < 32; i += 4) {
                float4 h0 = hh[i], h1 = hh[i + 1], h2 = hh[i + 2], h3 = hh[i + 3];
                a0 += w[i].x * h0.x + w[i].y * h0.y + w[i].z * h0.z + w[i].w * h0.w;
                a1 += w[i+1].x * h1.x + w[i+1].y * h1.y + w[i+1].z * h1.z + w[i+1].w * h1.w;
                a2 += w[i+2].x * h2.x + w[i+2].y * h2.y + w[i+2].z * h2.z + w[i+2].w * h2.w;
                a3 += w[i+3].x * h3.x + w[i+3].y * h3.y + w[i+3].z * h3.z + w[i+3].w * h3.w;
            }
            part[tid] = a0 + a1 + a2 + a3;
            __syncthreads();
            if (tid < 48) {
                float g = part[tid] + part[tid + 48] + part[tid + 96] + part[tid + 144] + bias;
                __stcg(gi_s + (size_t)t * G3 + row, g);
            }
            __threadfence();                 // every storer fences before barrier
            __syncthreads();                 // all fences complete
            if (tid == 0) __stcg(fArmy + cta, t + 1);
        }
    } else {
        // ================= SCAN: GRU recurrence =================
        for (int t = 0; t < T_LEN; ++t) {
            if (t > 0 && tid < 32) {
                while (ldcg_poll(fScan + tid) < t) { }
            }
            if (tid == 0) {
                while (ldcg_poll(fArmy + cta) < t + 1) { }
            }
            __syncthreads();
            __threadfence();   // acquire side (matches R7/R9 passing pattern)

            if (tid < 128) {
                if (t == 0) ((float4*)v_sh)[tid] = make_float4(0.f, 0.f, 0.f, 0.f);
                else ((float4*)v_sh)[tid] =
                    __ldcg((const float4*)(y_s + (size_t)(t - 1) * 512) + tid);
            }
            float gir = 0.f, giz = 0.f, gin_ = 0.f;
            if (tid < 16) {
                const float* g = gi_s + (size_t)t * G3;
                gir  = __ldcg(g + u0 + tid);
                giz  = __ldcg(g + 512 + u0 + tid);
                gin_ = __ldcg(g + 1024 + u0 + tid);
            }
            __syncthreads();
            float hprev = (tid < 16) ? v_sh[u0 + tid] : 0.0f;

            float a0 = 0.f, a1 = 0.f, a2 = 0.f, a3 = 0.f;
            const float4* hh = (const float4*)(v_sh + k0);
#pragma unroll
            for (int i = 0; i < 32; i += 4) {
                float4 h0 = hh[i], h1 = hh[i + 1], h2 = hh[i + 2], h3 = hh[i + 3];
                a0 += w[i].x * h0.x + w[i].y * h0.y + w[i].z * h0.z + w[i].w * h0.w;
                a1 += w[i+1].x * h1.x + w[i+1].y * h1.y + w[i+1].z * h1.z + w[i+1].w * h1.w;
                a2 += w[i+2].x * h2.x + w[i+2].y * h2.y + w[i+2].z * h2.z + w[i+2].w * h2.w;
                a3 += w[i+3].x * h3.x + w[i+3].y * h3.y + w[i+3].z * h3.z + w[i+3].w * h3.w;
            }
            part[tid] = a0 + a1 + a2 + a3;
            __syncthreads();
            if (tid < 48)
                g_sh[tid] = part[tid] + part[tid + 48] + part[tid + 96] + part[tid + 144] + bias;
            __syncthreads();
            if (tid < 16) {
                float rg = sigmoidf_(gir + g_sh[tid]);
                float zg = sigmoidf_(giz + g_sh[16 + tid]);
                float ng = tanhf(gin_ + rg * g_sh[32 + tid]);
                float hn = (1.0f - zg) * ng + zg * hprev;
                __stcg(y_s + (size_t)t * 512 + u0 + tid, hn);
            }
            if (tid < 32) {
                __threadfence();             // each storing lane fences its h-stores
                __syncwarp();                // all fences done before the flag
                if (tid == 0) __stcg(fScan + cta, t + 1);
            }
        }
    }
}

// ---------------------------------------------------------------------------
// Tail gi: out[s*2+t][n] = dot(x_{s,t}, W[n]) + b[n] for 4 vectors,
// each W row read ONCE.  grid 12 x 128 threads.
// ---------------------------------------------------------------------------
__global__ void tail_gi4_kernel(const float* __restrict__ W, const float* __restrict__ b,
                                const float* __restrict__ x00, const float* __restrict__ x01,
                                const float* __restrict__ x10, const float* __restrict__ x11,
                                float* __restrict__ out) {
    __shared__ __align__(16) float xs[4][512];
    int tid = threadIdx.x;   // 128
    ((float4*)xs[0])[tid] = __ldg((const float4*)x00 + tid);
    ((float4*)xs[1])[tid] = __ldg((const float4*)x01 + tid);
    ((float4*)xs[2])[tid] = __ldg((const float4*)x10 + tid);
    ((float4*)xs[3])[tid] = __ldg((const float4*)x11 + tid);
    __syncthreads();
    int n = blockIdx.x * 128 + tid;
    const float4* wr = (const float4*)(W + (size_t)n * 512);
    float a0 = 0.f, a1 = 0.f, a2 = 0.f, a3 = 0.f;
#pragma unroll 4
    for (int i = 0; i < 128; i++) {
        float4 wv = __ldg(wr + i);
        float4 v0 = ((const float4*)xs[0])[i];
        float4 v1 = ((const float4*)xs[1])[i];
        float4 v2 = ((const float4*)xs[2])[i];
        float4 v3 = ((const float4*)xs[3])[i];
        a0 += wv.x * v0.x + wv.y * v0.y + wv.z * v0.z + wv.w * v0.w;
        a1 += wv.x * v1.x + wv.y * v1.y + wv.z * v1.z + wv.w * v1.w;
        a2 += wv.x * v2.x + wv.y * v2.y + wv.z * v2.z + wv.w * v2.w;
        a3 += wv.x * v3.x + wv.y * v3.y + wv.z * v3.z + wv.w * v3.w;
    }
    float bb = b[n];
    out[(size_t)0 * G3 + n] = a0 + bb;
    out[(size_t)1 * G3 + n] = a1 + bb;
    out[(size_t)2 * G3 + n] = a2 + bb;
    out[(size_t)3 * G3 + n] = a3 + bb;
}

// ---------------------------------------------------------------------------
// Tiny-T cooperative GRU scan (T=2 uses only; counter-synced, R9-proven).
// ---------------------------------------------------------------------------
__global__ __launch_bounds__(STH, 1)
void gru_scan_kernel(const float* __restrict__ gi, const float* __restrict__ Whh,
                     const float* __restrict__ bhh, float* __restrict__ y,
                     int T, int cntBase) {
    const int C = NCTA;
    int s   = blockIdx.y;
    int cta = blockIdx.x;
    int tid = threadIdx.x;
    int r    = tid % 48;
    int q    = tid / 48;
    int gate = r / 16, ul = r % 16;
    int u0   = cta * 16;
    int row  = gate * 512 + u0 + ul;
    int k0   = q * 128;

    float4 w[32];
    const float4* wp = (const float4*)(Whh + (size_t)row * 512 + k0);
#pragma unroll
    for (int i = 0; i < 32; i++) w[i] = wp[i];
    float bh = (tid < 48) ? bhh[row] : 0.0f;

    __shared__ __align__(16) float h_sh[512];
    __shared__ float part[STH];
    __shared__ float gh_sh[48];

    const float* gi_s = gi + (size_t)s * T * G3;
    float* y_s = y + (size_t)s * T * 512;
    int* cnt_g = d_cnt + s * CNT_PER_GROUP + cntBase;

    for (int t = 0; t < T; ++t) {
        if (t == 0) {
            for (int i = tid; i < 512; i += STH) h_sh[i] = 0.0f;
        } else {
            if (tid == 0) {
                while (ldcg_poll(cnt_g + (t - 1)) < C) { }
            }
            __syncthreads();
            __threadfence();   // acquire side
            const float4* hp = (const float4*)(y_s + (size_t)(t - 1) * 512);
            for (int i = tid; i < 128; i += STH)
                ((float4*)h_sh)[i] = __ldcg(hp + i);
        }
        float gir = 0.f, giz = 0.f, gin_ = 0.f;
        if (tid < 16) {
            const float* g = gi_s + (size_t)t * G3;
            gir  = __ldg(g + u0 + tid);
            giz  = __ldg(g + 512 + u0 + tid);
            gin_ = __ldg(g + 1024 + u0 + tid);
        }
        __syncthreads();
        float hprev = (tid < 16) ? h_sh[u0 + tid] : 0.0f;

        float a0 = 0.f, a1 = 0.f, a2 = 0.f, a3 = 0.f;
        const float4* hh = (const float4*)(h_sh + k0);
#pragma unroll
        for (int i = 0; i < 32; i += 4) {
            float4 h0 = hh[i], h1 = hh[i + 1], h2 = hh[i + 2], h3 = hh[i + 3];
            a0 += w[i].x * h0.x + w[i].y * h0.y + w[i].z * h0.z + w[i].w * h0.w;
            a1 += w[i+1].x * h1.x + w[i+1].y * h1.y + w[i+1].z * h1.z + w[i+1].w * h1.w;
            a2 += w[i+2].x * h2.x + w[i+2].y * h2.y + w[i+2].z * h2.z + w[i+2].w * h2.w;
            a3 += w[i+3].x * h3.x + w[i+3].y * h3.y + w[i+3].z * h3.z + w[i+3].w * h3.w;
        }
        part[tid] = a0 + a1 + a2 + a3;
        __syncthreads();
        if (tid < 48)
            gh_sh[tid] = part[tid] + part[tid + 48] + part[tid + 96] + part[tid + 144] + bh;
        __syncthreads();
        if (tid < 16) {
            float rg = sigmoidf_(gir + gh_sh[tid]);
            float zg = sigmoidf_(giz + gh_sh[16 + tid]);
            float ng = tanhf(gin_ + rg * gh_sh[32 + tid]);
            float hn = (1.0f - zg) * ng + zg * hprev;
            __stcg(y_s + (size_t)t * 512 + u0 + tid, hn);
        }
        __syncthreads();
        __threadfence();       // every storer fences before the counter bump
        if (tid == 0) atomicAdd(cnt_g + t, 1);
    }
}

// ---------------------------------------------------------------------------
// conv1d + maxpool1d + gi2 (one CTA per sentence).
// ---------------------------------------------------------------------------
__global__ void conv_pool_gi2_kernel(const float* __restrict__ ys0, const float* __restrict__ ys1,
                                     const float* __restrict__ conv_w, const float* __restrict__ conv_b,
                                     const float* __restrict__ Wih2, const float* __restrict__ bih2,
                                     float* __restrict__ gi2) {
    int s = blockIdx.x;
    int tid = threadIdx.x;   // 256
    __shared__ float x_sh[2][512];
    __shared__ float y_sh[2][256];
    __shared__ float pooled[2][POOL_OUT];
    const float* c0 = ys0 + (size_t)(s * 2 + 1) * 512;
    const float* c1 = ys1 + (size_t)(s * 2 + 1) * 512;
    for (int i = tid; i < 512; i += 256) { x_sh[0][i] = c0[i]; x_sh[1][i] = c1[i]; }
    __syncthreads();

    for (int o = 0; o < 2; o++) {
        int j = tid;
        float acc = conv_b[o];
        int base = 2 * j - 255;
        for (int ic = 0; ic < 2; ic++) {
            const float* wr = conv_w + ((size_t)o * 2 + ic) * 512;
            int klo = base < 0 ? -base : 0;
            int khi = 512 - base; if (khi > 512) khi = 512;
            for (int k = klo; k < khi; k++) acc += x_sh[ic][base + k] * __ldg(wr + k);
        }
        y_sh[o][j] = acc;
    }
    __syncthreads();

    for (int i = tid; i < 2 * POOL_OUT; i += 256) {
        int o = i >> 7, p = i & 127;
        int lo = 2 * p - 255; if (lo < 0) lo = 0;
        int hi = 2 * p + 256; if (hi > 255) hi = 255;
        float m = -3.402823e38f;
        for (int qq = lo; qq <= hi; qq++) m = fmaxf(m, y_sh[o][qq]);
        pooled[o][p] = m;
    }
    __syncthreads();

    for (int i = tid; i < 2 * G3; i += 256) {
        int t = i / G3, n = i % G3;
        const float* wr = Wih2 + (size_t)n * POOL_OUT;
        float acc = bih2[n];
        for (int p = 0; p < POOL_OUT; p++) acc += pooled[t][p] * __ldg(wr + p);
        gi2[(size_t)(s * 2 + t) * G3 + n] = acc;
    }
}

// ---------------------------------------------------------------------------
// Final head.
// ---------------------------------------------------------------------------
__global__ void final_kernel(const float* __restrict__ ys2,
                             const float* __restrict__ WA, const float* __restrict__ WB,
                             const float* __restrict__ b_bi, const float* __restrict__ W_lin,
                             const float* __restrict__ b_lin, float* __restrict__ out) {
    __shared__ float hx[512], hv[512];
    __shared__ float red[256];
    const float* hA = ys2 + 1 * 512;
    const float* hB = ys2 + 3 * 512;
    int tid = threadIdx.x;             // 256
    for (int i = tid; i < 512; i += 256) {
        float a = hA[i], b = hB[i];
        hx[i] = a * b;
        hv[i] = fabsf(a - b);
    }
    __syncthreads();
    float acc = b_bi[tid];
    for (int h = 0; h < 512; h++)
        acc += hx[h] * __ldg(WA + (size_t)h * 256 + tid) + hv[h] * __ldg(WB + (size_t)h * 256 + tid);
    float ht = tanhf(acc);
    red[tid] = ht * __ldg(W_lin + tid);
    __syncthreads();
    for (int off = 128; off > 0; off >>= 1) {
        if (tid < off) red[tid] += red[tid + off];
        __syncthreads();
    }
    if (tid == 0) out[0] = 1.0f / (1.0f + expf(-(red[0] + b_lin[0])));
}

// ---------------------------------------------------------------------------
// Host launcher
// ---------------------------------------------------------------------------
static void* sym_addr(const void* sym) {
    void* p = nullptr;
    cudaGetSymbolAddress(&p, sym);
    return p;
}

extern "C" void kernel_launch(void* const* d_in, const int* in_sizes, int n_in,
                              void* d_out, int out_size) {
    const int*   sentA  = (const int*)  d_in[0];
    const int*   sentB  = (const int*)  d_in[1];
    const float* emb    = (const float*)d_in[2];
    const float* Wih1   = (const float*)d_in[3];   // [2][1536][512]
    const float* Whh1   = (const float*)d_in[4];   // [2][1536][512]
    const float* bih1   = (const float*)d_in[5];   // [2][1536]
    const float* bhh1   = (const float*)d_in[6];   // [2][1536]
    const float* conv_w = (const float*)d_in[7];   // [2][2][512]
    const float* conv_b = (const float*)d_in[8];   // [2]
    const float* Wih2   = (const float*)d_in[9];   // [1536][128]
    const float* Whh2   = (const float*)d_in[10];  // [1536][512]
    const float* bih2   = (const float*)d_in[11];  // [1536]
    const float* bhh2   = (const float*)d_in[12];  // [1536]
    const float* WA     = (const float*)d_in[13];  // [512][256]
    const float* WB     = (const float*)d_in[14];  // [512][256]
    const float* b_bi   = (const float*)d_in[15];  // [256]
    const float* W_lin  = (const float*)d_in[16];  // [1][256]
    const float* b_lin  = (const float*)d_in[17];  // [1]
    (void)in_sizes; (void)n_in; (void)out_size;

    float* pgi  = (float*)sym_addr(d_gi);
    float* pyl0 = (float*)sym_addr(d_yl0);
    float* pyl1 = (float*)sym_addr(d_yl1);
    float* pgis = (float*)sym_addr(d_gis);
    float* pys0 = (float*)sym_addr(d_ys0);
    float* pys1 = (float*)sym_addr(d_ys1);
    float* pys2 = (float*)sym_addr(d_ys2);

    const float* Wih1_l1 = Wih1 + (size_t)G3 * 512;
    const float* Whh1_l1 = Whh1 + (size_t)G3 * 512;
    const float* bih1_l1 = bih1 + G3;
    const float* bhh1_l1 = bhh1 + G3;

    dim3 layer_grid(NCTA, 2, 2);            // ctas x roles x sentences
    dim3 scan_grid(NCTA, 2);

    // 0. reset flags/counters (graph-replay safe)
    zero_cnt_kernel<<<6, 256>>>();

    // ---- epoch 0, layer 0: army gathers emb + computes gi; scan recurses ----
    scan_layer_kernel<<<layer_grid, STH>>>(Wih1, bih1, Whh1, bhh1,
                                           emb, sentA, sentB, pgi, pyl0, 0);
    // ---- epoch 0, layer 1: army consumes y0 (prev launch, fully ready) ----
    scan_layer_kernel<<<layer_grid, STH>>>(Wih1_l1, bih1_l1, Whh1_l1, bhh1_l1,
                                           pyl0, nullptr, nullptr, pgi, pyl1, 1);

    // ---- epoch 1 (sequence = stacked finals of epoch 0, length 2) ----
    tail_gi4_kernel<<<12, 128>>>(Wih1, bih1,
                                 pyl0 + 255 * 512, pyl1 + 255 * 512,
                                 pyl0 + (T_LEN + 255) * 512, pyl1 + (T_LEN + 255) * 512,
                                 pgis);
    gru_scan_kernel<<<scan_grid, STH>>>(pgis, Whh1, bhh1, pys0, 2, 512);
    tail_gi4_kernel<<<12, 128>>>(Wih1_l1, bih1_l1,
                                 pys0, pys0 + 512, pys0 + 1024, pys0 + 1536,
                                 pgis);
    gru_scan_kernel<<<scan_grid, STH>>>(pgis, Whh1_l1, bhh1_l1, pys1, 2, 514);

    // ---- conv + pool + gi2 ----
    conv_pool_gi2_kernel<<<2, 256>>>(pys0, pys1, conv_w, conv_b, Wih2, bih2, pgis);

    // ---- rnn_second (length 2) ----
    gru_scan_kernel<<<scan_grid, STH>>>(pgis, Whh2, bhh2, pys2, 2, 516);

    // ---- head ----
    final_kernel<<<1, 256>>>(pys2, WA, WB, b_bi, W_lin, b_lin, (float*)d_out);
}